// round 4
// baseline (speedup 1.0000x reference)
#include <cuda_runtime.h>
#include <cuda_bf16.h>
#include <cstdint>

#define D_IN     256
#define H_DIM    128
#define N_SHARE  4
#define N_EXPERTS 12        // 4 shared + 2 tasks * 4 experts
#define M_TILE   64
#define KCHUNK   64
#define XS_STRIDE 260       // 260 % 32 == 4 -> conflict-free A-frag LDS
#define WS_STRIDE 136       // 136 % 32 == 8 -> conflict-free B-frag LDS
#define THREADS  256

// shared memory layout (floats)
#define OFF_XS    0
#define SZ_XS     (M_TILE * XS_STRIDE)          // 16640
#define OFF_WS    (OFF_XS + SZ_XS)
#define SZ_WS     (2 * KCHUNK * WS_STRIDE)      // 17408
#define OFF_WG    (OFF_WS + SZ_WS)
#define WG_TSTRIDE 2056                         // 2048 + 8 pad
#define SZ_WG     (2 * WG_TSTRIDE)              // 4112
#define OFF_GATE  (OFF_WG + SZ_WG)
#define SZ_GATE   (M_TILE * 17)                 // 1088
#define OFF_BIAS  (OFF_GATE + SZ_GATE)
#define SZ_BIAS   (N_EXPERTS * H_DIM)           // 1536
#define SMEM_FLOATS (OFF_BIAS + SZ_BIAS)        // 40784
#define SMEM_BYTES  (SMEM_FLOATS * 4)           // 163136

__device__ __forceinline__ unsigned f2tf(float x) {
    unsigned u;
    asm("cvt.rna.tf32.f32 %0, %1;" : "=r"(u) : "f"(x));
    return u;
}

__device__ __forceinline__ void mma_tf32(float* d, const unsigned* a, const unsigned* b) {
    asm volatile(
        "mma.sync.aligned.m16n8k8.row.col.f32.tf32.tf32.f32 "
        "{%0,%1,%2,%3}, {%4,%5,%6,%7}, {%8,%9}, {%0,%1,%2,%3};\n"
        : "+f"(d[0]), "+f"(d[1]), "+f"(d[2]), "+f"(d[3])
        : "r"(a[0]), "r"(a[1]), "r"(a[2]), "r"(a[3]),
          "r"(b[0]), "r"(b[1]));
}

__global__ __launch_bounds__(THREADS, 1)
void dmoe_fused_kernel(const float* __restrict__ x,
                       const float* __restrict__ Wsh,
                       const float* __restrict__ bsh,
                       const float* __restrict__ Wtk,
                       const float* __restrict__ btk,
                       const float* __restrict__ Wg,
                       const float* __restrict__ bg,
                       float* __restrict__ out,
                       int Btot)
{
    extern __shared__ float sm[];
    float* xs  = sm + OFF_XS;
    float* ws  = sm + OFF_WS;
    float* wgs = sm + OFF_WG;
    float* gs  = sm + OFF_GATE;
    float* bs  = sm + OFF_BIAS;

    const int tid  = threadIdx.x;
    const int warp = tid >> 5;
    const int lane = tid & 31;
    const int gid  = lane >> 2;          // 0..7
    const int tig  = lane & 3;           // 0..3
    const int m0   = (warp >> 2) * 32;   // 0 or 32
    const int h0   = (warp & 3) * 32;    // 0,32,64,96
    const int row0 = blockIdx.x * M_TILE;

    // issue one 64-k weight chunk (2048 float4) via cp.async into buffer `buf`
    auto issue_chunk = [&](int e, int kc, int buf) {
        const float* wsrc = (e < N_SHARE)
            ? (Wsh + (size_t)e * (D_IN * H_DIM))
            : (Wtk + (size_t)(e - N_SHARE) * (D_IN * H_DIM));
        wsrc += kc * KCHUNK * H_DIM;
        float* wdst = ws + buf * (KCHUNK * WS_STRIDE);
        #pragma unroll
        for (int j = 0; j < 8; ++j) {
            int idx = j * THREADS + tid;     // float4 index, 2048 total
            int r   = idx >> 5;              // 0..63
            int c4  = idx & 31;              // 0..31
            const float* g = wsrc + r * H_DIM + c4 * 4;
            unsigned saddr = (unsigned)__cvta_generic_to_shared(wdst + r * WS_STRIDE + c4 * 4);
            asm volatile("cp.async.ca.shared.global [%0], [%1], 16;\n"
                         :: "r"(saddr), "l"(g));
        }
        asm volatile("cp.async.commit_group;\n" ::: "memory");
    };

    // --- prologue: kick off weight chunk 0 immediately
    issue_chunk(0, 0, 0);

    // --- stage x tile (64 x 256), RNA-rounded to tf32
    {
        const float4* xg = (const float4*)(x + (size_t)row0 * D_IN);
        #pragma unroll
        for (int j = 0; j < 16; ++j) {
            int idx = j * THREADS + tid;     // 4096 float4
            int r   = idx >> 6;
            int c4  = idx & 63;
            float4 v = xg[r * 64 + c4];
            v.x = __uint_as_float(f2tf(v.x));
            v.y = __uint_as_float(f2tf(v.y));
            v.z = __uint_as_float(f2tf(v.z));
            v.w = __uint_as_float(f2tf(v.w));
            *(float4*)(xs + r * XS_STRIDE + c4 * 4) = v;
        }
    }
    // --- stage W_gate [2][256][8] (full fp32)
    {
        const float4* wgg = (const float4*)Wg;
        #pragma unroll
        for (int j = 0; j < 4; ++j) {
            int idx = j * THREADS + tid;     // 1024 float4
            int t   = idx >> 9;
            int rem = idx & 511;             // float4 within task
            float4 v = wgg[idx];
            *(float4*)(wgs + t * WG_TSTRIDE + rem * 4) = v;
        }
    }
    // --- stage expert biases [12][128]
    for (int i = tid; i < SZ_BIAS; i += THREADS) {
        int e = i >> 7, h = i & 127;
        bs[i] = (e < N_SHARE) ? bsh[e * H_DIM + h]
                              : btk[(e - N_SHARE) * H_DIM + h];
    }
    __syncthreads();

    // --- gates: each warp handles row-pairs (warp + 8*i).
    // lanes 0..15 -> even row, lanes 16..31 -> odd row; within 16 lanes: gi = t*8+g
    {
        int half = lane >> 4;
        int gi   = lane & 15;
        int t    = gi >> 3;
        int gg   = gi & 7;
        const float* wcol = wgs + t * WG_TSTRIDE + gg;
        float bias = bg[t * 8 + gg];
        #pragma unroll
        for (int i = 0; i < 4; ++i) {
            int p   = warp + 8 * i;
            int row = 2 * p + half;
            const float* xr = xs + row * XS_STRIDE;
            float acc = 0.f;
            #pragma unroll 8
            for (int k = 0; k < D_IN; ++k)
                acc = fmaf(xr[k], wcol[k * 8], acc);
            acc += bias;
            float mx = acc;
            mx = fmaxf(mx, __shfl_xor_sync(0xffffffffu, mx, 1));
            mx = fmaxf(mx, __shfl_xor_sync(0xffffffffu, mx, 2));
            mx = fmaxf(mx, __shfl_xor_sync(0xffffffffu, mx, 4));
            float ev = __expf(acc - mx);
            float s = ev;
            s += __shfl_xor_sync(0xffffffffu, s, 1);
            s += __shfl_xor_sync(0xffffffffu, s, 2);
            s += __shfl_xor_sync(0xffffffffu, s, 4);
            gs[row * 17 + gi] = ev / s;
        }
    }
    __syncthreads();

    // --- towers accumulators (registers): tw[task][mt][nt][c]
    float tw[2][2][4][4];
    #pragma unroll
    for (int t = 0; t < 2; ++t)
        #pragma unroll
        for (int mt = 0; mt < 2; ++mt)
            #pragma unroll
            for (int nt = 0; nt < 4; ++nt)
                #pragma unroll
                for (int c = 0; c < 4; ++c)
                    tw[t][mt][nt][c] = 0.f;

    // --- main loop: 12 experts x 4 k-chunks, double-buffered cp.async
    #pragma unroll 1
    for (int e = 0; e < N_EXPERTS; ++e) {
        float acc[2][4][4];
        #pragma unroll
        for (int mt = 0; mt < 2; ++mt)
            #pragma unroll
            for (int nt = 0; nt < 4; ++nt)
                #pragma unroll
                for (int c = 0; c < 4; ++c)
                    acc[mt][nt][c] = 0.f;

        #pragma unroll 1
        for (int kc = 0; kc < 4; ++kc) {
            int buf    = kc & 1;
            int nchunk = e * 4 + kc + 1;
            if (nchunk < N_EXPERTS * 4) {
                issue_chunk(nchunk >> 2, nchunk & 3, (kc + 1) & 1);
                asm volatile("cp.async.wait_group 1;\n" ::: "memory");
            } else {
                asm volatile("cp.async.wait_group 0;\n" ::: "memory");
            }
            __syncthreads();

            const float* wb = ws + buf * (KCHUNK * WS_STRIDE);
            #pragma unroll
            for (int ks = 0; ks < 8; ++ks) {
                int kk = kc * KCHUNK + ks * 8;
                unsigned a[2][4];
                #pragma unroll
                for (int mt = 0; mt < 2; ++mt) {
                    const float* xr = xs + (m0 + mt * 16 + gid) * XS_STRIDE + kk;
                    a[mt][0] = __float_as_uint(xr[tig]);
                    a[mt][1] = __float_as_uint(xr[8 * XS_STRIDE + tig]);
                    a[mt][2] = __float_as_uint(xr[tig + 4]);
                    a[mt][3] = __float_as_uint(xr[8 * XS_STRIDE + tig + 4]);
                }
                unsigned b[4][2];
                const float* wr = wb + (ks * 8 + tig) * WS_STRIDE + h0 + gid;
                #pragma unroll
                for (int nt = 0; nt < 4; ++nt) {
                    b[nt][0] = f2tf(wr[nt * 8]);
                    b[nt][1] = f2tf(wr[nt * 8 + 4 * WS_STRIDE]);
                }
                #pragma unroll
                for (int mt = 0; mt < 2; ++mt)
                    #pragma unroll
                    for (int nt = 0; nt < 4; ++nt)
                        mma_tf32(acc[mt][nt], a[mt], b[nt]);
            }
            __syncthreads();
        }

        // --- epilogue for expert e: bias + ReLU + gate-weighted accumulate
        #pragma unroll
        for (int mt = 0; mt < 2; ++mt) {
            int rA = m0 + mt * 16 + gid;
            int rB = rA + 8;
            if (e < N_SHARE) {
                // shared expert: contributes to both tasks (gate cols e and 8+e)
                float gA0 = gs[rA * 17 + e],     gB0 = gs[rB * 17 + e];
                float gA1 = gs[rA * 17 + 8 + e], gB1 = gs[rB * 17 + 8 + e];
                #pragma unroll
                for (int nt = 0; nt < 4; ++nt) {
                    int h = h0 + nt * 8 + tig * 2;
                    float b0 = bs[e * H_DIM + h];
                    float b1 = bs[e * H_DIM + h + 1];
                    float v0 = fmaxf(acc[mt][nt][0] + b0, 0.f);
                    float v1 = fmaxf(acc[mt][nt][1] + b1, 0.f);
                    float v2 = fmaxf(acc[mt][nt][2] + b0, 0.f);
                    float v3 = fmaxf(acc[mt][nt][3] + b1, 0.f);
                    tw[0][mt][nt][0] += gA0 * v0;  tw[0][mt][nt][1] += gA0 * v1;
                    tw[0][mt][nt][2] += gB0 * v2;  tw[0][mt][nt][3] += gB0 * v3;
                    tw[1][mt][nt][0] += gA1 * v0;  tw[1][mt][nt][1] += gA1 * v1;
                    tw[1][mt][nt][2] += gB1 * v2;  tw[1][mt][nt][3] += gB1 * v3;
                }
            } else {
                int et   = e - N_SHARE;
                int tt   = et >> 2;                    // task 0 or 1
                int gcol = tt * 8 + 4 + (et & 3);      // gate column
                float gA = gs[rA * 17 + gcol];
                float gB = gs[rB * 17 + gcol];
                if (tt == 0) {
                    #pragma unroll
                    for (int nt = 0; nt < 4; ++nt) {
                        int h = h0 + nt * 8 + tig * 2;
                        float b0 = bs[e * H_DIM + h];
                        float b1 = bs[e * H_DIM + h + 1];
                        tw[0][mt][nt][0] += gA * fmaxf(acc[mt][nt][0] + b0, 0.f);
                        tw[0][mt][nt][1] += gA * fmaxf(acc[mt][nt][1] + b1, 0.f);
                        tw[0][mt][nt][2] += gB * fmaxf(acc[mt][nt][2] + b0, 0.f);
                        tw[0][mt][nt][3] += gB * fmaxf(acc[mt][nt][3] + b1, 0.f);
                    }
                } else {
                    #pragma unroll
                    for (int nt = 0; nt < 4; ++nt) {
                        int h = h0 + nt * 8 + tig * 2;
                        float b0 = bs[e * H_DIM + h];
                        float b1 = bs[e * H_DIM + h + 1];
                        tw[1][mt][nt][0] += gA * fmaxf(acc[mt][nt][0] + b0, 0.f);
                        tw[1][mt][nt][1] += gA * fmaxf(acc[mt][nt][1] + b1, 0.f);
                        tw[1][mt][nt][2] += gB * fmaxf(acc[mt][nt][2] + b0, 0.f);
                        tw[1][mt][nt][3] += gB * fmaxf(acc[mt][nt][3] + b1, 0.f);
                    }
                }
            }
        }
    }

    // --- write towers [2][B][128]
    #pragma unroll
    for (int t = 0; t < 2; ++t) {
        #pragma unroll
        for (int mt = 0; mt < 2; ++mt) {
            size_t rA = (size_t)row0 + m0 + mt * 16 + gid;
            float* baseA = out + ((size_t)t * Btot + rA) * H_DIM;
            float* baseB = baseA + 8 * H_DIM;
            #pragma unroll
            for (int nt = 0; nt < 4; ++nt) {
                int h = h0 + nt * 8 + tig * 2;
                *(float2*)(baseA + h) = make_float2(tw[t][mt][nt][0], tw[t][mt][nt][1]);
                *(float2*)(baseB + h) = make_float2(tw[t][mt][nt][2], tw[t][mt][nt][3]);
            }
        }
    }
}

extern "C" void kernel_launch(void* const* d_in, const int* in_sizes, int n_in,
                              void* d_out, int out_size) {
    const float* x   = (const float*)d_in[0];
    const float* Wsh = (const float*)d_in[1];
    const float* bsh = (const float*)d_in[2];
    const float* Wtk = (const float*)d_in[3];
    const float* btk = (const float*)d_in[4];
    const float* Wg  = (const float*)d_in[5];
    const float* bg  = (const float*)d_in[6];
    float* out = (float*)d_out;

    int Btot = in_sizes[0] / D_IN;          // 32768
    int grid = Btot / M_TILE;               // 512

    cudaFuncSetAttribute(dmoe_fused_kernel,
                         cudaFuncAttributeMaxDynamicSharedMemorySize, SMEM_BYTES);
    dmoe_fused_kernel<<<grid, THREADS, SMEM_BYTES>>>(x, Wsh, bsh, Wtk, btk, Wg, bg, out, Btot);
}

// round 5
// speedup vs baseline: 1.0008x; 1.0008x over previous
#include <cuda_runtime.h>
#include <cuda_bf16.h>
#include <cstdint>

#define D_IN     256
#define H_DIM    128
#define N_SHARE  4
#define N_EXPERTS 12        // 4 shared + 2 tasks * 4 experts
#define M_TILE   64
#define KCHUNK   64
#define XS_STRIDE 260       // 260 % 32 == 4 -> conflict-free A-frag LDS
#define WS_STRIDE 136       // 136 % 32 == 8 -> conflict-free B-frag LDS
#define THREADS  256

// shared memory layout (floats)
#define OFF_XS    0
#define SZ_XS     (M_TILE * XS_STRIDE)          // 16640
#define OFF_WS    (OFF_XS + SZ_XS)
#define SZ_WS     (2 * KCHUNK * WS_STRIDE)      // 17408
#define OFF_WG    (OFF_WS + SZ_WS)
#define WG_TSTRIDE 2056                         // 2048 + 8 pad
#define SZ_WG     (2 * WG_TSTRIDE)              // 4112
#define OFF_GATE  (OFF_WG + SZ_WG)
#define SZ_GATE   (M_TILE * 17)                 // 1088
#define OFF_BIAS  (OFF_GATE + SZ_GATE)
#define SZ_BIAS   (N_EXPERTS * H_DIM)           // 1536
#define SMEM_FLOATS (OFF_BIAS + SZ_BIAS)        // 40784
#define SMEM_BYTES  (SMEM_FLOATS * 4)           // 163136

__device__ __forceinline__ unsigned f2tf(float x) {
    unsigned u;
    asm("cvt.rna.tf32.f32 %0, %1;" : "=r"(u) : "f"(x));
    return u;
}

__device__ __forceinline__ void mma_tf32(float* d, const unsigned* a, const unsigned* b) {
    asm volatile(
        "mma.sync.aligned.m16n8k8.row.col.f32.tf32.tf32.f32 "
        "{%0,%1,%2,%3}, {%4,%5,%6,%7}, {%8,%9}, {%0,%1,%2,%3};\n"
        : "+f"(d[0]), "+f"(d[1]), "+f"(d[2]), "+f"(d[3])
        : "r"(a[0]), "r"(a[1]), "r"(a[2]), "r"(a[3]),
          "r"(b[0]), "r"(b[1]));
}

__global__ __launch_bounds__(THREADS, 1)
void dmoe_fused_kernel(const float* __restrict__ x,
                       const float* __restrict__ Wsh,
                       const float* __restrict__ bsh,
                       const float* __restrict__ Wtk,
                       const float* __restrict__ btk,
                       const float* __restrict__ Wg,
                       const float* __restrict__ bg,
                       float* __restrict__ out,
                       int Btot)
{
    extern __shared__ float sm[];
    float* xs  = sm + OFF_XS;
    float* ws  = sm + OFF_WS;
    float* wgs = sm + OFF_WG;
    float* gs  = sm + OFF_GATE;
    float* bs  = sm + OFF_BIAS;

    const int tid  = threadIdx.x;
    const int warp = tid >> 5;
    const int lane = tid & 31;
    const int gid  = lane >> 2;          // 0..7
    const int tig  = lane & 3;           // 0..3
    const int m0   = (warp >> 2) * 32;   // 0 or 32
    const int h0   = (warp & 3) * 32;    // 0,32,64,96
    const int row0 = blockIdx.x * M_TILE;

    // issue one 64-k weight chunk (2048 float4) via cp.async into buffer `buf`
    auto issue_chunk = [&](int e, int kc, int buf) {
        const float* wsrc = (e < N_SHARE)
            ? (Wsh + (size_t)e * (D_IN * H_DIM))
            : (Wtk + (size_t)(e - N_SHARE) * (D_IN * H_DIM));
        wsrc += kc * KCHUNK * H_DIM;
        float* wdst = ws + buf * (KCHUNK * WS_STRIDE);
        #pragma unroll
        for (int j = 0; j < 8; ++j) {
            int idx = j * THREADS + tid;     // float4 index, 2048 total
            int r   = idx >> 5;              // 0..63
            int c4  = idx & 31;              // 0..31
            const float* g = wsrc + r * H_DIM + c4 * 4;
            unsigned saddr = (unsigned)__cvta_generic_to_shared(wdst + r * WS_STRIDE + c4 * 4);
            asm volatile("cp.async.ca.shared.global [%0], [%1], 16;\n"
                         :: "r"(saddr), "l"(g));
        }
        asm volatile("cp.async.commit_group;\n" ::: "memory");
    };

    // --- prologue: kick off weight chunk 0 immediately
    issue_chunk(0, 0, 0);

    // --- stage x tile (64 x 256), RNA-rounded to tf32
    {
        const float4* xg = (const float4*)(x + (size_t)row0 * D_IN);
        #pragma unroll
        for (int j = 0; j < 16; ++j) {
            int idx = j * THREADS + tid;     // 4096 float4
            int r   = idx >> 6;
            int c4  = idx & 63;
            float4 v = xg[r * 64 + c4];
            v.x = __uint_as_float(f2tf(v.x));
            v.y = __uint_as_float(f2tf(v.y));
            v.z = __uint_as_float(f2tf(v.z));
            v.w = __uint_as_float(f2tf(v.w));
            *(float4*)(xs + r * XS_STRIDE + c4 * 4) = v;
        }
    }
    // --- stage W_gate [2][256][8] (full fp32)
    {
        const float4* wgg = (const float4*)Wg;
        #pragma unroll
        for (int j = 0; j < 4; ++j) {
            int idx = j * THREADS + tid;     // 1024 float4
            int t   = idx >> 9;
            int rem = idx & 511;             // float4 within task
            float4 v = wgg[idx];
            *(float4*)(wgs + t * WG_TSTRIDE + rem * 4) = v;
        }
    }
    // --- stage expert biases [12][128]
    for (int i = tid; i < SZ_BIAS; i += THREADS) {
        int e = i >> 7, h = i & 127;
        bs[i] = (e < N_SHARE) ? bsh[e * H_DIM + h]
                              : btk[(e - N_SHARE) * H_DIM + h];
    }
    __syncthreads();

    // --- gates: each warp handles row-pairs (warp + 8*i).
    // lanes 0..15 -> even row, lanes 16..31 -> odd row; within 16 lanes: gi = t*8+g
    {
        int half = lane >> 4;
        int gi   = lane & 15;
        int t    = gi >> 3;
        int gg   = gi & 7;
        const float* wcol = wgs + t * WG_TSTRIDE + gg;
        float bias = bg[t * 8 + gg];
        #pragma unroll
        for (int i = 0; i < 4; ++i) {
            int p   = warp + 8 * i;
            int row = 2 * p + half;
            const float* xr = xs + row * XS_STRIDE;
            float acc = 0.f;
            #pragma unroll 8
            for (int k = 0; k < D_IN; ++k)
                acc = fmaf(xr[k], wcol[k * 8], acc);
            acc += bias;
            float mx = acc;
            mx = fmaxf(mx, __shfl_xor_sync(0xffffffffu, mx, 1));
            mx = fmaxf(mx, __shfl_xor_sync(0xffffffffu, mx, 2));
            mx = fmaxf(mx, __shfl_xor_sync(0xffffffffu, mx, 4));
            float ev = __expf(acc - mx);
            float s = ev;
            s += __shfl_xor_sync(0xffffffffu, s, 1);
            s += __shfl_xor_sync(0xffffffffu, s, 2);
            s += __shfl_xor_sync(0xffffffffu, s, 4);
            gs[row * 17 + gi] = ev / s;
        }
    }
    __syncthreads();

    // --- towers accumulators (registers): tw[task][mt][nt][c]
    float tw[2][2][4][4];
    #pragma unroll
    for (int t = 0; t < 2; ++t)
        #pragma unroll
        for (int mt = 0; mt < 2; ++mt)
            #pragma unroll
            for (int nt = 0; nt < 4; ++nt)
                #pragma unroll
                for (int c = 0; c < 4; ++c)
                    tw[t][mt][nt][c] = 0.f;

    // --- main loop: 12 experts x 4 k-chunks, double-buffered cp.async
    #pragma unroll 1
    for (int e = 0; e < N_EXPERTS; ++e) {
        float acc[2][4][4];
        #pragma unroll
        for (int mt = 0; mt < 2; ++mt)
            #pragma unroll
            for (int nt = 0; nt < 4; ++nt)
                #pragma unroll
                for (int c = 0; c < 4; ++c)
                    acc[mt][nt][c] = 0.f;

        #pragma unroll 1
        for (int kc = 0; kc < 4; ++kc) {
            int buf    = kc & 1;
            int nchunk = e * 4 + kc + 1;
            if (nchunk < N_EXPERTS * 4) {
                issue_chunk(nchunk >> 2, nchunk & 3, (kc + 1) & 1);
                asm volatile("cp.async.wait_group 1;\n" ::: "memory");
            } else {
                asm volatile("cp.async.wait_group 0;\n" ::: "memory");
            }
            __syncthreads();

            const float* wb = ws + buf * (KCHUNK * WS_STRIDE);
            #pragma unroll
            for (int ks = 0; ks < 8; ++ks) {
                int kk = kc * KCHUNK + ks * 8;
                unsigned a[2][4];
                #pragma unroll
                for (int mt = 0; mt < 2; ++mt) {
                    const float* xr = xs + (m0 + mt * 16 + gid) * XS_STRIDE + kk;
                    a[mt][0] = __float_as_uint(xr[tig]);
                    a[mt][1] = __float_as_uint(xr[8 * XS_STRIDE + tig]);
                    a[mt][2] = __float_as_uint(xr[tig + 4]);
                    a[mt][3] = __float_as_uint(xr[8 * XS_STRIDE + tig + 4]);
                }
                unsigned b[4][2];
                const float* wr = wb + (ks * 8 + tig) * WS_STRIDE + h0 + gid;
                #pragma unroll
                for (int nt = 0; nt < 4; ++nt) {
                    b[nt][0] = f2tf(wr[nt * 8]);
                    b[nt][1] = f2tf(wr[nt * 8 + 4 * WS_STRIDE]);
                }
                #pragma unroll
                for (int mt = 0; mt < 2; ++mt)
                    #pragma unroll
                    for (int nt = 0; nt < 4; ++nt)
                        mma_tf32(acc[mt][nt], a[mt], b[nt]);
            }
            __syncthreads();
        }

        // --- epilogue for expert e: bias + ReLU + gate-weighted accumulate
        #pragma unroll
        for (int mt = 0; mt < 2; ++mt) {
            int rA = m0 + mt * 16 + gid;
            int rB = rA + 8;
            if (e < N_SHARE) {
                // shared expert: contributes to both tasks (gate cols e and 8+e)
                float gA0 = gs[rA * 17 + e],     gB0 = gs[rB * 17 + e];
                float gA1 = gs[rA * 17 + 8 + e], gB1 = gs[rB * 17 + 8 + e];
                #pragma unroll
                for (int nt = 0; nt < 4; ++nt) {
                    int h = h0 + nt * 8 + tig * 2;
                    float b0 = bs[e * H_DIM + h];
                    float b1 = bs[e * H_DIM + h + 1];
                    float v0 = fmaxf(acc[mt][nt][0] + b0, 0.f);
                    float v1 = fmaxf(acc[mt][nt][1] + b1, 0.f);
                    float v2 = fmaxf(acc[mt][nt][2] + b0, 0.f);
                    float v3 = fmaxf(acc[mt][nt][3] + b1, 0.f);
                    tw[0][mt][nt][0] += gA0 * v0;  tw[0][mt][nt][1] += gA0 * v1;
                    tw[0][mt][nt][2] += gB0 * v2;  tw[0][mt][nt][3] += gB0 * v3;
                    tw[1][mt][nt][0] += gA1 * v0;  tw[1][mt][nt][1] += gA1 * v1;
                    tw[1][mt][nt][2] += gB1 * v2;  tw[1][mt][nt][3] += gB1 * v3;
                }
            } else {
                int et   = e - N_SHARE;
                int tt   = et >> 2;                    // task 0 or 1
                int gcol = tt * 8 + 4 + (et & 3);      // gate column
                float gA = gs[rA * 17 + gcol];
                float gB = gs[rB * 17 + gcol];
                if (tt == 0) {
                    #pragma unroll
                    for (int nt = 0; nt < 4; ++nt) {
                        int h = h0 + nt * 8 + tig * 2;
                        float b0 = bs[e * H_DIM + h];
                        float b1 = bs[e * H_DIM + h + 1];
                        tw[0][mt][nt][0] += gA * fmaxf(acc[mt][nt][0] + b0, 0.f);
                        tw[0][mt][nt][1] += gA * fmaxf(acc[mt][nt][1] + b1, 0.f);
                        tw[0][mt][nt][2] += gB * fmaxf(acc[mt][nt][2] + b0, 0.f);
                        tw[0][mt][nt][3] += gB * fmaxf(acc[mt][nt][3] + b1, 0.f);
                    }
                } else {
                    #pragma unroll
                    for (int nt = 0; nt < 4; ++nt) {
                        int h = h0 + nt * 8 + tig * 2;
                        float b0 = bs[e * H_DIM + h];
                        float b1 = bs[e * H_DIM + h + 1];
                        tw[1][mt][nt][0] += gA * fmaxf(acc[mt][nt][0] + b0, 0.f);
                        tw[1][mt][nt][1] += gA * fmaxf(acc[mt][nt][1] + b1, 0.f);
                        tw[1][mt][nt][2] += gB * fmaxf(acc[mt][nt][2] + b0, 0.f);
                        tw[1][mt][nt][3] += gB * fmaxf(acc[mt][nt][3] + b1, 0.f);
                    }
                }
            }
        }
    }

    // --- write towers [2][B][128]
    #pragma unroll
    for (int t = 0; t < 2; ++t) {
        #pragma unroll
        for (int mt = 0; mt < 2; ++mt) {
            size_t rA = (size_t)row0 + m0 + mt * 16 + gid;
            float* baseA = out + ((size_t)t * Btot + rA) * H_DIM;
            float* baseB = baseA + 8 * H_DIM;
            #pragma unroll
            for (int nt = 0; nt < 4; ++nt) {
                int h = h0 + nt * 8 + tig * 2;
                *(float2*)(baseA + h) = make_float2(tw[t][mt][nt][0], tw[t][mt][nt][1]);
                *(float2*)(baseB + h) = make_float2(tw[t][mt][nt][2], tw[t][mt][nt][3]);
            }
        }
    }
}

extern "C" void kernel_launch(void* const* d_in, const int* in_sizes, int n_in,
                              void* d_out, int out_size) {
    const float* x   = (const float*)d_in[0];
    const float* Wsh = (const float*)d_in[1];
    const float* bsh = (const float*)d_in[2];
    const float* Wtk = (const float*)d_in[3];
    const float* btk = (const float*)d_in[4];
    const float* Wg  = (const float*)d_in[5];
    const float* bg  = (const float*)d_in[6];
    float* out = (float*)d_out;

    int Btot = in_sizes[0] / D_IN;          // 32768
    int grid = Btot / M_TILE;               // 512

    cudaFuncSetAttribute(dmoe_fused_kernel,
                         cudaFuncAttributeMaxDynamicSharedMemorySize, SMEM_BYTES);
    dmoe_fused_kernel<<<grid, THREADS, SMEM_BYTES>>>(x, Wsh, bsh, Wtk, btk, Wg, bg, out, Btot);
}

// round 6
// speedup vs baseline: 1.0041x; 1.0033x over previous
#include <cuda_runtime.h>
#include <cuda_bf16.h>
#include <cstdint>

#define D_IN     256
#define H_DIM    128
#define N_SHARE  4
#define N_EXPERTS 12        // 4 shared + 2 tasks * 4 experts
#define M_TILE   64
#define KCHUNK   64
#define XS_STRIDE 260       // 260 % 32 == 4 -> conflict-free A-frag LDS
#define WS_STRIDE 136       // 136 % 32 == 8 -> conflict-free B-frag LDS
#define THREADS  256

// shared memory layout (floats)
#define OFF_XS    0
#define SZ_XS     (M_TILE * XS_STRIDE)          // 16640
#define OFF_WS    (OFF_XS + SZ_XS)
#define SZ_WS     (2 * KCHUNK * WS_STRIDE)      // 17408
#define OFF_WG    (OFF_WS + SZ_WS)
#define WG_TSTRIDE 2056                         // 2048 + 8 pad
#define SZ_WG     (2 * WG_TSTRIDE)              // 4112
#define OFF_GATE  (OFF_WG + SZ_WG)
#define SZ_GATE   (M_TILE * 17)                 // 1088
#define OFF_BIAS  (OFF_GATE + SZ_GATE)
#define SZ_BIAS   (N_EXPERTS * H_DIM)           // 1536
#define SMEM_FLOATS (OFF_BIAS + SZ_BIAS)        // 40784
#define SMEM_BYTES  (SMEM_FLOATS * 4)           // 163136

__device__ __forceinline__ unsigned f2tf(float x) {
    unsigned u;
    asm("cvt.rna.tf32.f32 %0, %1;" : "=r"(u) : "f"(x));
    return u;
}

__device__ __forceinline__ void mma_tf32(float* d, const unsigned* a, const unsigned* b) {
    asm volatile(
        "mma.sync.aligned.m16n8k8.row.col.f32.tf32.tf32.f32 "
        "{%0,%1,%2,%3}, {%4,%5,%6,%7}, {%8,%9}, {%0,%1,%2,%3};\n"
        : "+f"(d[0]), "+f"(d[1]), "+f"(d[2]), "+f"(d[3])
        : "r"(a[0]), "r"(a[1]), "r"(a[2]), "r"(a[3]),
          "r"(b[0]), "r"(b[1]));
}

__global__ __launch_bounds__(THREADS, 1)
void dmoe_fused_kernel(const float* __restrict__ x,
                       const float* __restrict__ Wsh,
                       const float* __restrict__ bsh,
                       const float* __restrict__ Wtk,
                       const float* __restrict__ btk,
                       const float* __restrict__ Wg,
                       const float* __restrict__ bg,
                       float* __restrict__ out,
                       int Btot)
{
    extern __shared__ float sm[];
    float* xs  = sm + OFF_XS;
    float* ws  = sm + OFF_WS;
    float* wgs = sm + OFF_WG;
    float* gs  = sm + OFF_GATE;
    float* bs  = sm + OFF_BIAS;

    const int tid  = threadIdx.x;
    const int warp = tid >> 5;
    const int lane = tid & 31;
    const int gid  = lane >> 2;          // 0..7
    const int tig  = lane & 3;           // 0..3
    const int m0   = (warp >> 2) * 32;   // 0 or 32
    const int h0   = (warp & 3) * 32;    // 0,32,64,96
    const int row0 = blockIdx.x * M_TILE;

    // issue one 64-k weight chunk (2048 float4) via cp.async into buffer `buf`
    auto issue_chunk = [&](int e, int kc, int buf) {
        const float* wsrc = (e < N_SHARE)
            ? (Wsh + (size_t)e * (D_IN * H_DIM))
            : (Wtk + (size_t)(e - N_SHARE) * (D_IN * H_DIM));
        wsrc += kc * KCHUNK * H_DIM;
        float* wdst = ws + buf * (KCHUNK * WS_STRIDE);
        #pragma unroll
        for (int j = 0; j < 8; ++j) {
            int idx = j * THREADS + tid;     // float4 index, 2048 total
            int r   = idx >> 5;              // 0..63
            int c4  = idx & 31;              // 0..31
            const float* g = wsrc + r * H_DIM + c4 * 4;
            unsigned saddr = (unsigned)__cvta_generic_to_shared(wdst + r * WS_STRIDE + c4 * 4);
            asm volatile("cp.async.ca.shared.global [%0], [%1], 16;\n"
                         :: "r"(saddr), "l"(g));
        }
        asm volatile("cp.async.commit_group;\n" ::: "memory");
    };

    // --- prologue: kick off weight chunk 0 immediately
    issue_chunk(0, 0, 0);

    // --- stage x tile (64 x 256), RNA-rounded to tf32
    {
        const float4* xg = (const float4*)(x + (size_t)row0 * D_IN);
        #pragma unroll
        for (int j = 0; j < 16; ++j) {
            int idx = j * THREADS + tid;     // 4096 float4
            int r   = idx >> 6;
            int c4  = idx & 63;
            float4 v = xg[r * 64 + c4];
            v.x = __uint_as_float(f2tf(v.x));
            v.y = __uint_as_float(f2tf(v.y));
            v.z = __uint_as_float(f2tf(v.z));
            v.w = __uint_as_float(f2tf(v.w));
            *(float4*)(xs + r * XS_STRIDE + c4 * 4) = v;
        }
    }
    // --- stage W_gate [2][256][8] (full fp32)
    {
        const float4* wgg = (const float4*)Wg;
        #pragma unroll
        for (int j = 0; j < 4; ++j) {
            int idx = j * THREADS + tid;     // 1024 float4
            int t   = idx >> 9;
            int rem = idx & 511;             // float4 within task
            float4 v = wgg[idx];
            *(float4*)(wgs + t * WG_TSTRIDE + rem * 4) = v;
        }
    }
    // --- stage expert biases [12][128]
    for (int i = tid; i < SZ_BIAS; i += THREADS) {
        int e = i >> 7, h = i & 127;
        bs[i] = (e < N_SHARE) ? bsh[e * H_DIM + h]
                              : btk[(e - N_SHARE) * H_DIM + h];
    }
    __syncthreads();

    // --- gates: each warp handles row-pairs (warp + 8*i).
    // lanes 0..15 -> even row, lanes 16..31 -> odd row; within 16 lanes: gi = t*8+g
    {
        int half = lane >> 4;
        int gi   = lane & 15;
        int t    = gi >> 3;
        int gg   = gi & 7;
        const float* wcol = wgs + t * WG_TSTRIDE + gg;
        float bias = bg[t * 8 + gg];
        #pragma unroll
        for (int i = 0; i < 4; ++i) {
            int p   = warp + 8 * i;
            int row = 2 * p + half;
            const float* xr = xs + row * XS_STRIDE;
            float acc = 0.f;
            #pragma unroll 8
            for (int k = 0; k < D_IN; ++k)
                acc = fmaf(xr[k], wcol[k * 8], acc);
            acc += bias;
            float mx = acc;
            mx = fmaxf(mx, __shfl_xor_sync(0xffffffffu, mx, 1));
            mx = fmaxf(mx, __shfl_xor_sync(0xffffffffu, mx, 2));
            mx = fmaxf(mx, __shfl_xor_sync(0xffffffffu, mx, 4));
            float ev = __expf(acc - mx);
            float s = ev;
            s += __shfl_xor_sync(0xffffffffu, s, 1);
            s += __shfl_xor_sync(0xffffffffu, s, 2);
            s += __shfl_xor_sync(0xffffffffu, s, 4);
            gs[row * 17 + gi] = ev / s;
        }
    }
    __syncthreads();

    // --- towers accumulators (registers): tw[task][mt][nt][c]
    float tw[2][2][4][4];
    #pragma unroll
    for (int t = 0; t < 2; ++t)
        #pragma unroll
        for (int mt = 0; mt < 2; ++mt)
            #pragma unroll
            for (int nt = 0; nt < 4; ++nt)
                #pragma unroll
                for (int c = 0; c < 4; ++c)
                    tw[t][mt][nt][c] = 0.f;

    // --- main loop: 12 experts x 4 k-chunks, double-buffered cp.async
    #pragma unroll 1
    for (int e = 0; e < N_EXPERTS; ++e) {
        float acc[2][4][4];
        #pragma unroll
        for (int mt = 0; mt < 2; ++mt)
            #pragma unroll
            for (int nt = 0; nt < 4; ++nt)
                #pragma unroll
                for (int c = 0; c < 4; ++c)
                    acc[mt][nt][c] = 0.f;

        #pragma unroll 1
        for (int kc = 0; kc < 4; ++kc) {
            int buf    = kc & 1;
            int nchunk = e * 4 + kc + 1;
            if (nchunk < N_EXPERTS * 4) {
                issue_chunk(nchunk >> 2, nchunk & 3, (kc + 1) & 1);
                asm volatile("cp.async.wait_group 1;\n" ::: "memory");
            } else {
                asm volatile("cp.async.wait_group 0;\n" ::: "memory");
            }
            __syncthreads();

            const float* wb = ws + buf * (KCHUNK * WS_STRIDE);
            #pragma unroll
            for (int ks = 0; ks < 8; ++ks) {
                int kk = kc * KCHUNK + ks * 8;
                unsigned a[2][4];
                #pragma unroll
                for (int mt = 0; mt < 2; ++mt) {
                    const float* xr = xs + (m0 + mt * 16 + gid) * XS_STRIDE + kk;
                    a[mt][0] = __float_as_uint(xr[tig]);
                    a[mt][1] = __float_as_uint(xr[8 * XS_STRIDE + tig]);
                    a[mt][2] = __float_as_uint(xr[tig + 4]);
                    a[mt][3] = __float_as_uint(xr[8 * XS_STRIDE + tig + 4]);
                }
                unsigned b[4][2];
                const float* wr = wb + (ks * 8 + tig) * WS_STRIDE + h0 + gid;
                #pragma unroll
                for (int nt = 0; nt < 4; ++nt) {
                    b[nt][0] = f2tf(wr[nt * 8]);
                    b[nt][1] = f2tf(wr[nt * 8 + 4 * WS_STRIDE]);
                }
                #pragma unroll
                for (int mt = 0; mt < 2; ++mt)
                    #pragma unroll
                    for (int nt = 0; nt < 4; ++nt)
                        mma_tf32(acc[mt][nt], a[mt], b[nt]);
            }
            __syncthreads();
        }

        // --- epilogue for expert e: bias + ReLU + gate-weighted accumulate
        #pragma unroll
        for (int mt = 0; mt < 2; ++mt) {
            int rA = m0 + mt * 16 + gid;
            int rB = rA + 8;
            if (e < N_SHARE) {
                // shared expert: contributes to both tasks (gate cols e and 8+e)
                float gA0 = gs[rA * 17 + e],     gB0 = gs[rB * 17 + e];
                float gA1 = gs[rA * 17 + 8 + e], gB1 = gs[rB * 17 + 8 + e];
                #pragma unroll
                for (int nt = 0; nt < 4; ++nt) {
                    int h = h0 + nt * 8 + tig * 2;
                    float b0 = bs[e * H_DIM + h];
                    float b1 = bs[e * H_DIM + h + 1];
                    float v0 = fmaxf(acc[mt][nt][0] + b0, 0.f);
                    float v1 = fmaxf(acc[mt][nt][1] + b1, 0.f);
                    float v2 = fmaxf(acc[mt][nt][2] + b0, 0.f);
                    float v3 = fmaxf(acc[mt][nt][3] + b1, 0.f);
                    tw[0][mt][nt][0] += gA0 * v0;  tw[0][mt][nt][1] += gA0 * v1;
                    tw[0][mt][nt][2] += gB0 * v2;  tw[0][mt][nt][3] += gB0 * v3;
                    tw[1][mt][nt][0] += gA1 * v0;  tw[1][mt][nt][1] += gA1 * v1;
                    tw[1][mt][nt][2] += gB1 * v2;  tw[1][mt][nt][3] += gB1 * v3;
                }
            } else {
                int et   = e - N_SHARE;
                int tt   = et >> 2;                    // task 0 or 1
                int gcol = tt * 8 + 4 + (et & 3);      // gate column
                float gA = gs[rA * 17 + gcol];
                float gB = gs[rB * 17 + gcol];
                if (tt == 0) {
                    #pragma unroll
                    for (int nt = 0; nt < 4; ++nt) {
                        int h = h0 + nt * 8 + tig * 2;
                        float b0 = bs[e * H_DIM + h];
                        float b1 = bs[e * H_DIM + h + 1];
                        tw[0][mt][nt][0] += gA * fmaxf(acc[mt][nt][0] + b0, 0.f);
                        tw[0][mt][nt][1] += gA * fmaxf(acc[mt][nt][1] + b1, 0.f);
                        tw[0][mt][nt][2] += gB * fmaxf(acc[mt][nt][2] + b0, 0.f);
                        tw[0][mt][nt][3] += gB * fmaxf(acc[mt][nt][3] + b1, 0.f);
                    }
                } else {
                    #pragma unroll
                    for (int nt = 0; nt < 4; ++nt) {
                        int h = h0 + nt * 8 + tig * 2;
                        float b0 = bs[e * H_DIM + h];
                        float b1 = bs[e * H_DIM + h + 1];
                        tw[1][mt][nt][0] += gA * fmaxf(acc[mt][nt][0] + b0, 0.f);
                        tw[1][mt][nt][1] += gA * fmaxf(acc[mt][nt][1] + b1, 0.f);
                        tw[1][mt][nt][2] += gB * fmaxf(acc[mt][nt][2] + b0, 0.f);
                        tw[1][mt][nt][3] += gB * fmaxf(acc[mt][nt][3] + b1, 0.f);
                    }
                }
            }
        }
    }

    // --- write towers [2][B][128]
    #pragma unroll
    for (int t = 0; t < 2; ++t) {
        #pragma unroll
        for (int mt = 0; mt < 2; ++mt) {
            size_t rA = (size_t)row0 + m0 + mt * 16 + gid;
            float* baseA = out + ((size_t)t * Btot + rA) * H_DIM;
            float* baseB = baseA + 8 * H_DIM;
            #pragma unroll
            for (int nt = 0; nt < 4; ++nt) {
                int h = h0 + nt * 8 + tig * 2;
                *(float2*)(baseA + h) = make_float2(tw[t][mt][nt][0], tw[t][mt][nt][1]);
                *(float2*)(baseB + h) = make_float2(tw[t][mt][nt][2], tw[t][mt][nt][3]);
            }
        }
    }
}

extern "C" void kernel_launch(void* const* d_in, const int* in_sizes, int n_in,
                              void* d_out, int out_size) {
    const float* x   = (const float*)d_in[0];
    const float* Wsh = (const float*)d_in[1];
    const float* bsh = (const float*)d_in[2];
    const float* Wtk = (const float*)d_in[3];
    const float* btk = (const float*)d_in[4];
    const float* Wg  = (const float*)d_in[5];
    const float* bg  = (const float*)d_in[6];
    float* out = (float*)d_out;

    int Btot = in_sizes[0] / D_IN;          // 32768
    int grid = Btot / M_TILE;               // 512

    cudaFuncSetAttribute(dmoe_fused_kernel,
                         cudaFuncAttributeMaxDynamicSharedMemorySize, SMEM_BYTES);
    dmoe_fused_kernel<<<grid, THREADS, SMEM_BYTES>>>(x, Wsh, bsh, Wtk, btk, Wg, bg, out, Btot);
}